// round 2
// baseline (speedup 1.0000x reference)
#include <cuda_runtime.h>
#include <math.h>

#define TT   1024
#define SSZ  1024
#define BB   4
#define DD   1024
#define HH   16
#define HDD  64
#define FFND 4096
#define MM   (TT*BB)   // 4096 rows for [T,B,D] flattened

// ---------------- scratch (device globals; no allocs allowed) ----------------
__device__ float g_q[MM*DD];
__device__ float g_k[MM*DD];
__device__ float g_v[MM*DD];
__device__ float g_ctx[MM*DD];
__device__ float g_tmp[MM*DD];
__device__ float g_x1[MM*DD];
__device__ float g_x2[MM*DD];
__device__ float g_ffn[(size_t)MM*FFND];
__device__ float g_scores[(size_t)BB*HH*TT*SSZ];   // 256 MB
__device__ float g_rs_self[MM];
__device__ float g_rs_enc[MM];

// ---------------- helpers ----------------
__device__ __forceinline__ float block_sum(float v) {
    __shared__ float sh[8];
    __shared__ float res;
    int lane = threadIdx.x & 31, w = threadIdx.x >> 5;
    #pragma unroll
    for (int o = 16; o > 0; o >>= 1) v += __shfl_xor_sync(0xffffffffu, v, o);
    __syncthreads();
    if (lane == 0) sh[w] = v;
    __syncthreads();
    if (threadIdx.x == 0) {
        float t = 0.f;
        #pragma unroll
        for (int i = 0; i < 8; i++) t += sh[i];
        res = t;
    }
    __syncthreads();
    return res;
}

__device__ __forceinline__ float block_max(float v) {
    __shared__ float sh[8];
    __shared__ float res;
    int lane = threadIdx.x & 31, w = threadIdx.x >> 5;
    #pragma unroll
    for (int o = 16; o > 0; o >>= 1) v = fmaxf(v, __shfl_xor_sync(0xffffffffu, v, o));
    __syncthreads();
    if (lane == 0) sh[w] = v;
    __syncthreads();
    if (threadIdx.x == 0) {
        float t = sh[0];
        #pragma unroll
        for (int i = 1; i < 8; i++) t = fmaxf(t, sh[i]);
        res = t;
    }
    __syncthreads();
    return res;
}

// ---------------- mask expansion: rowscale[r = pos*B + b] = mask[b][pos] ? 0 : 1
// masks arrive as int32 (bool promoted by the harness)
__global__ void expand_mask_kernel(const int* __restrict__ mask,
                                   float* __restrict__ rowscale, int L) {
    int r = blockIdx.x * blockDim.x + threadIdx.x;
    if (r < L * BB) {
        int pos = r / BB, b = r % BB;
        rowscale[r] = mask[b * L + pos] ? 0.f : 1.f;
    }
}

// ---------------- SGEMM: C[M,N] = A[M,K] @ W[N,K]^T + bias  (opt relu, opt rowscale on A)
#define GBM 128
#define GBN 128
#define GBK 16
__global__ __launch_bounds__(256) void sgemm_kernel(
    const float* __restrict__ A, const float* __restrict__ W,
    const float* __restrict__ bias, const float* __restrict__ rowscale,
    float* __restrict__ C, int M, int N, int K, int relu)
{
    __shared__ float As[GBK][GBM];
    __shared__ float Ws[GBK][GBN];
    const int tid = threadIdx.x;
    const int tx = tid & 15, ty = tid >> 4;
    const int bx = blockIdx.x, by = blockIdx.y;

    float acc[8][8];
    #pragma unroll
    for (int i = 0; i < 8; i++)
        #pragma unroll
        for (int j = 0; j < 8; j++) acc[i][j] = 0.f;

    for (int k0 = 0; k0 < K; k0 += GBK) {
        #pragma unroll
        for (int i = 0; i < 2; i++) {
            int v = tid + (i << 8);
            int r = v >> 2;
            int c4 = (v & 3) << 2;
            int gr = by * GBM + r;
            float4 a = *(const float4*)(A + (size_t)gr * K + k0 + c4);
            if (rowscale) { float s = rowscale[gr]; a.x *= s; a.y *= s; a.z *= s; a.w *= s; }
            As[c4 + 0][r] = a.x; As[c4 + 1][r] = a.y; As[c4 + 2][r] = a.z; As[c4 + 3][r] = a.w;
        }
        #pragma unroll
        for (int i = 0; i < 2; i++) {
            int v = tid + (i << 8);
            int r = v >> 2;
            int c4 = (v & 3) << 2;
            int gr = bx * GBN + r;
            float4 w = *(const float4*)(W + (size_t)gr * K + k0 + c4);
            Ws[c4 + 0][r] = w.x; Ws[c4 + 1][r] = w.y; Ws[c4 + 2][r] = w.z; Ws[c4 + 3][r] = w.w;
        }
        __syncthreads();
        #pragma unroll
        for (int k = 0; k < GBK; k++) {
            float4 a0 = *(const float4*)&As[k][ty * 8];
            float4 a1 = *(const float4*)&As[k][ty * 8 + 4];
            float4 w0 = *(const float4*)&Ws[k][tx * 8];
            float4 w1 = *(const float4*)&Ws[k][tx * 8 + 4];
            float af[8] = {a0.x, a0.y, a0.z, a0.w, a1.x, a1.y, a1.z, a1.w};
            float wf[8] = {w0.x, w0.y, w0.z, w0.w, w1.x, w1.y, w1.z, w1.w};
            #pragma unroll
            for (int i = 0; i < 8; i++)
                #pragma unroll
                for (int j = 0; j < 8; j++) acc[i][j] += af[i] * wf[j];
        }
        __syncthreads();
    }

    int row0 = by * GBM + ty * 8;
    int col0 = bx * GBN + tx * 8;
    float breg[8];
    #pragma unroll
    for (int j = 0; j < 8; j++) breg[j] = bias[col0 + j];
    #pragma unroll
    for (int i = 0; i < 8; i++) {
        float4 o0, o1;
        o0.x = acc[i][0] + breg[0]; o0.y = acc[i][1] + breg[1];
        o0.z = acc[i][2] + breg[2]; o0.w = acc[i][3] + breg[3];
        o1.x = acc[i][4] + breg[4]; o1.y = acc[i][5] + breg[5];
        o1.z = acc[i][6] + breg[6]; o1.w = acc[i][7] + breg[7];
        if (relu) {
            o0.x = fmaxf(o0.x, 0.f); o0.y = fmaxf(o0.y, 0.f);
            o0.z = fmaxf(o0.z, 0.f); o0.w = fmaxf(o0.w, 0.f);
            o1.x = fmaxf(o1.x, 0.f); o1.y = fmaxf(o1.y, 0.f);
            o1.z = fmaxf(o1.z, 0.f); o1.w = fmaxf(o1.w, 0.f);
        }
        *(float4*)(C + (size_t)(row0 + i) * N + col0)     = o0;
        *(float4*)(C + (size_t)(row0 + i) * N + col0 + 4) = o1;
    }
}

// ---------------- attention scores: Sc[bh,t,s] = scale * Q·K + optional mask[t,s]
__global__ __launch_bounds__(256) void scores_kernel(
    const float* __restrict__ Q, const float* __restrict__ Kk,
    const float* __restrict__ mask, float* __restrict__ Sc, float scale)
{
    __shared__ float Qs[HDD][64 + 1];
    __shared__ float Ks[HDD][64 + 1];
    int bh = blockIdx.z;
    int b = bh / HH, h = bh % HH;
    int t0 = blockIdx.y * 64, s0 = blockIdx.x * 64;
    int tid = threadIdx.x, tx = tid & 15, ty = tid >> 4;

    #pragma unroll
    for (int i = 0; i < 4; i++) {
        int v = tid + (i << 8);
        int r = v >> 4;
        int c4 = (v & 15) << 2;
        float4 q = *(const float4*)(Q + ((size_t)(t0 + r) * BB + b) * DD + h * HDD + c4);
        Qs[c4 + 0][r] = q.x; Qs[c4 + 1][r] = q.y; Qs[c4 + 2][r] = q.z; Qs[c4 + 3][r] = q.w;
        float4 kk = *(const float4*)(Kk + ((size_t)(s0 + r) * BB + b) * DD + h * HDD + c4);
        Ks[c4 + 0][r] = kk.x; Ks[c4 + 1][r] = kk.y; Ks[c4 + 2][r] = kk.z; Ks[c4 + 3][r] = kk.w;
    }
    __syncthreads();

    float acc[4][4];
    #pragma unroll
    for (int i = 0; i < 4; i++)
        #pragma unroll
        for (int j = 0; j < 4; j++) acc[i][j] = 0.f;

    #pragma unroll
    for (int k = 0; k < HDD; k++) {
        float qf[4], kf[4];
        #pragma unroll
        for (int i = 0; i < 4; i++) qf[i] = Qs[k][ty * 4 + i];
        #pragma unroll
        for (int j = 0; j < 4; j++) kf[j] = Ks[k][tx * 4 + j];
        #pragma unroll
        for (int i = 0; i < 4; i++)
            #pragma unroll
            for (int j = 0; j < 4; j++) acc[i][j] += qf[i] * kf[j];
    }

    #pragma unroll
    for (int i = 0; i < 4; i++) {
        int t = t0 + ty * 4 + i;
        #pragma unroll
        for (int j = 0; j < 4; j++) {
            int s = s0 + tx * 4 + j;
            float c = acc[i][j] * scale;
            if (mask) c += mask[(size_t)t * TT + s];
            Sc[((size_t)bh * TT + t) * SSZ + s] = c;
        }
    }
}

// ---------------- softmax over last dim (1024), one block per row
__global__ __launch_bounds__(256) void softmax_kernel(float* __restrict__ Sc) {
    float* p = Sc + (size_t)blockIdx.x * SSZ;
    int tid = threadIdx.x;
    float4 v = *(float4*)(p + tid * 4);
    float m = fmaxf(fmaxf(v.x, v.y), fmaxf(v.z, v.w));
    m = block_max(m);
    float e0 = __expf(v.x - m), e1 = __expf(v.y - m);
    float e2 = __expf(v.z - m), e3 = __expf(v.w - m);
    float s = block_sum(e0 + e1 + e2 + e3);
    float inv = 1.f / s;
    float4 o; o.x = e0 * inv; o.y = e1 * inv; o.z = e2 * inv; o.w = e3 * inv;
    *(float4*)(p + tid * 4) = o;
}

// ---------------- ctx: [t,hd] = P[t,:] @ V[:,hd] per (b,h); also writes attn [h,b,t,hd]
__global__ __launch_bounds__(256) void ctx_kernel(
    const float* __restrict__ P, const float* __restrict__ V,
    float* __restrict__ ctx, float* __restrict__ attn)
{
    __shared__ float Ps[32][64 + 1];
    __shared__ float Vs[32][68];
    int bh = blockIdx.y;
    int b = bh / HH, h = bh % HH;
    int t0 = blockIdx.x * 64;
    int tid = threadIdx.x, tx = tid & 15, ty = tid >> 4;
    const float* Pb = P + (size_t)bh * TT * SSZ;

    float acc[4][4];
    #pragma unroll
    for (int i = 0; i < 4; i++)
        #pragma unroll
        for (int j = 0; j < 4; j++) acc[i][j] = 0.f;

    for (int s0 = 0; s0 < SSZ; s0 += 32) {
        #pragma unroll
        for (int i = 0; i < 2; i++) {
            int v = tid + (i << 8);
            int r = v >> 3;
            int c4 = (v & 7) << 2;
            float4 p4 = *(const float4*)(Pb + (size_t)(t0 + r) * SSZ + s0 + c4);
            Ps[c4 + 0][r] = p4.x; Ps[c4 + 1][r] = p4.y; Ps[c4 + 2][r] = p4.z; Ps[c4 + 3][r] = p4.w;
        }
        #pragma unroll
        for (int i = 0; i < 2; i++) {
            int v = tid + (i << 8);
            int r = v >> 4;
            int c4 = (v & 15) << 2;
            float4 v4 = *(const float4*)(V + ((size_t)(s0 + r) * BB + b) * DD + h * HDD + c4);
            *(float4*)&Vs[r][c4] = v4;
        }
        __syncthreads();
        #pragma unroll
        for (int k = 0; k < 32; k++) {
            float pf[4], vf[4];
            #pragma unroll
            for (int i = 0; i < 4; i++) pf[i] = Ps[k][ty * 4 + i];
            #pragma unroll
            for (int j = 0; j < 4; j++) vf[j] = Vs[k][tx * 4 + j];
            #pragma unroll
            for (int i = 0; i < 4; i++)
                #pragma unroll
                for (int j = 0; j < 4; j++) acc[i][j] += pf[i] * vf[j];
        }
        __syncthreads();
    }

    #pragma unroll
    for (int i = 0; i < 4; i++) {
        int t = t0 + ty * 4 + i;
        #pragma unroll
        for (int j = 0; j < 4; j++) {
            int hd = tx * 4 + j;
            float c = acc[i][j];
            ctx[((size_t)t * BB + b) * DD + h * HDD + hd] = c;
            if (attn) attn[(((size_t)h * BB + b) * TT + t) * HDD + hd] = c;
        }
    }
}

// ---------------- fused residual add + layernorm (one block per row of 1024)
__global__ __launch_bounds__(256) void add_ln_kernel(
    const float* __restrict__ a, const float* __restrict__ r,
    const float* __restrict__ g, const float* __restrict__ be,
    float* __restrict__ o)
{
    size_t row = blockIdx.x;
    int tid = threadIdx.x;
    float4 va = *(const float4*)(a + row * DD + tid * 4);
    float4 vr = *(const float4*)(r + row * DD + tid * 4);
    float x0 = va.x + vr.x, x1 = va.y + vr.y, x2 = va.z + vr.z, x3 = va.w + vr.w;
    float s  = block_sum(x0 + x1 + x2 + x3);
    float mu = s * (1.f / DD);
    float d0 = x0 - mu, d1 = x1 - mu, d2 = x2 - mu, d3 = x3 - mu;
    float sq = block_sum(d0 * d0 + d1 * d1 + d2 * d2 + d3 * d3);
    float inv = rsqrtf(sq * (1.f / DD) + 1e-5f);
    float4 vg = *(const float4*)(g + tid * 4);
    float4 vb = *(const float4*)(be + tid * 4);
    float4 out;
    out.x = d0 * inv * vg.x + vb.x;
    out.y = d1 * inv * vg.y + vb.y;
    out.z = d2 * inv * vg.z + vb.z;
    out.w = d3 * inv * vg.w + vb.w;
    *(float4*)(o + row * DD + tid * 4) = out;
}

// ---------------- host launch ----------------
extern "C" void kernel_launch(void* const* d_in, const int* in_sizes, int n_in,
                              void* d_out, int out_size)
{
    const float* state = (const float*)d_in[0];
    const float* enc   = (const float*)d_in[1];
    const float* amask = (const float*)d_in[2];
    const int* spad = (const int*)d_in[3];
    const int* epad = (const int*)d_in[4];
    const float *saWq = (const float*)d_in[5],  *sabq = (const float*)d_in[6];
    const float *saWk = (const float*)d_in[7],  *sabk = (const float*)d_in[8];
    const float *saWv = (const float*)d_in[9],  *sabv = (const float*)d_in[10];
    const float *saWo = (const float*)d_in[11], *sabo = (const float*)d_in[12];
    const float *eaWq = (const float*)d_in[13], *eabq = (const float*)d_in[14];
    const float *eaWk = (const float*)d_in[15], *eabk = (const float*)d_in[16];
    const float *eaWv = (const float*)d_in[17], *eabv = (const float*)d_in[18];
    const float *eaWo = (const float*)d_in[19], *eabo = (const float*)d_in[20];
    const float *ln1g = (const float*)d_in[21], *ln1b = (const float*)d_in[22];
    const float *ln2g = (const float*)d_in[23], *ln2b = (const float*)d_in[24];
    const float *ln3g = (const float*)d_in[25], *ln3b = (const float*)d_in[26];
    const float *fc1W = (const float*)d_in[27], *fc1b = (const float*)d_in[28];
    const float *fc2W = (const float*)d_in[29], *fc2b = (const float*)d_in[30];

    float *q, *k, *v, *ctx, *tmp, *x1, *x2, *ffn, *sc, *rss, *rse;
    cudaGetSymbolAddress((void**)&q,   g_q);
    cudaGetSymbolAddress((void**)&k,   g_k);
    cudaGetSymbolAddress((void**)&v,   g_v);
    cudaGetSymbolAddress((void**)&ctx, g_ctx);
    cudaGetSymbolAddress((void**)&tmp, g_tmp);
    cudaGetSymbolAddress((void**)&x1,  g_x1);
    cudaGetSymbolAddress((void**)&x2,  g_x2);
    cudaGetSymbolAddress((void**)&ffn, g_ffn);
    cudaGetSymbolAddress((void**)&sc,  g_scores);
    cudaGetSymbolAddress((void**)&rss, g_rs_self);
    cudaGetSymbolAddress((void**)&rse, g_rs_enc);

    float* outx = (float*)d_out;
    float* outa = outx + (size_t)MM * DD;

    const float scale = 0.125f;  // 1/sqrt(64)

    expand_mask_kernel<<<(MM + 255) / 256, 256>>>(spad, rss, TT);
    expand_mask_kernel<<<(MM + 255) / 256, 256>>>(epad, rse, SSZ);

    dim3 gProj(DD / GBN, MM / GBM);           // (8, 32)
    dim3 gF1(FFND / GBN, MM / GBM);           // (32, 32)
    dim3 gSc(SSZ / 64, TT / 64, BB * HH);     // (16, 16, 64)
    dim3 gCtx(TT / 64, BB * HH);              // (16, 64)

    // ---- self-attention block ----
    sgemm_kernel<<<gProj, 256>>>(state, saWq, sabq, nullptr, q, MM, DD, DD, 0);
    sgemm_kernel<<<gProj, 256>>>(state, saWk, sabk, rss,     k, MM, DD, DD, 0);
    sgemm_kernel<<<gProj, 256>>>(state, saWv, sabv, nullptr, v, MM, DD, DD, 0);
    scores_kernel<<<gSc, 256>>>(q, k, amask, sc, scale);
    softmax_kernel<<<BB * HH * TT, 256>>>(sc);
    ctx_kernel<<<gCtx, 256>>>(sc, v, ctx, nullptr);
    sgemm_kernel<<<gProj, 256>>>(ctx, saWo, sabo, nullptr, tmp, MM, DD, DD, 0);
    add_ln_kernel<<<MM, 256>>>(tmp, state, ln1g, ln1b, x1);

    // ---- encoder-decoder attention block ----
    sgemm_kernel<<<gProj, 256>>>(x1,  eaWq, eabq, nullptr, q, MM, DD, DD, 0);
    sgemm_kernel<<<gProj, 256>>>(enc, eaWk, eabk, rse,     k, MM, DD, DD, 0);
    sgemm_kernel<<<gProj, 256>>>(enc, eaWv, eabv, nullptr, v, MM, DD, DD, 0);
    scores_kernel<<<gSc, 256>>>(q, k, nullptr, sc, scale);
    softmax_kernel<<<BB * HH * TT, 256>>>(sc);
    ctx_kernel<<<gCtx, 256>>>(sc, v, ctx, outa);
    sgemm_kernel<<<gProj, 256>>>(ctx, eaWo, eabo, nullptr, tmp, MM, DD, DD, 0);
    add_ln_kernel<<<MM, 256>>>(tmp, x1, ln2g, ln2b, x2);

    // ---- FFN block ----
    sgemm_kernel<<<gF1, 256>>>(x2, fc1W, fc1b, nullptr, ffn, MM, FFND, DD, 1);
    sgemm_kernel<<<gProj, 256>>>(ffn, fc2W, fc2b, nullptr, tmp, MM, DD, FFND, 0);
    add_ln_kernel<<<MM, 256>>>(tmp, x2, ln3g, ln3b, outx);
}

// round 3
// speedup vs baseline: 2.4088x; 2.4088x over previous
#include <cuda_runtime.h>
#include <math.h>
#include <stdint.h>

#define TT   1024
#define SSZ  1024
#define BB   4
#define DD   1024
#define HH   16
#define HDD  64
#define FFND 4096
#define MM   (TT*BB)   // 4096 rows for [T,B,D] flattened

// ---------------- scratch (device globals; no allocs allowed) ----------------
__device__ float g_q[MM*DD];
__device__ float g_k[MM*DD];
__device__ float g_v[MM*DD];
__device__ float g_ctx[MM*DD];
__device__ float g_tmp[MM*DD];
__device__ float g_x1[MM*DD];
__device__ float g_x2[MM*DD];
__device__ float g_ffn[(size_t)MM*FFND];
__device__ float g_scores[(size_t)BB*HH*TT*SSZ];   // 256 MB
__device__ float g_rs_self[MM];
__device__ float g_rs_enc[MM];

// ---------------- helpers ----------------
__device__ __forceinline__ float block_sum(float v) {
    __shared__ float sh[8];
    __shared__ float res;
    int lane = threadIdx.x & 31, w = threadIdx.x >> 5;
    #pragma unroll
    for (int o = 16; o > 0; o >>= 1) v += __shfl_xor_sync(0xffffffffu, v, o);
    __syncthreads();
    if (lane == 0) sh[w] = v;
    __syncthreads();
    if (threadIdx.x == 0) {
        float t = 0.f;
        #pragma unroll
        for (int i = 0; i < 8; i++) t += sh[i];
        res = t;
    }
    __syncthreads();
    return res;
}

__device__ __forceinline__ float block_max(float v) {
    __shared__ float sh[8];
    __shared__ float res;
    int lane = threadIdx.x & 31, w = threadIdx.x >> 5;
    #pragma unroll
    for (int o = 16; o > 0; o >>= 1) v = fmaxf(v, __shfl_xor_sync(0xffffffffu, v, o));
    __syncthreads();
    if (lane == 0) sh[w] = v;
    __syncthreads();
    if (threadIdx.x == 0) {
        float t = sh[0];
        #pragma unroll
        for (int i = 1; i < 8; i++) t = fmaxf(t, sh[i]);
        res = t;
    }
    __syncthreads();
    return res;
}

// tf32 conversion + mma.m16n8k8 helpers
__device__ __forceinline__ uint32_t f2tf32(float x) {
    uint32_t u;
    asm("cvt.rna.tf32.f32 %0, %1;" : "=r"(u) : "f"(x));
    return u;
}

__device__ __forceinline__ void mma_tf32(float* d, const uint32_t* a, uint32_t b0, uint32_t b1) {
    asm volatile(
        "mma.sync.aligned.m16n8k8.row.col.f32.tf32.tf32.f32 "
        "{%0,%1,%2,%3}, {%4,%5,%6,%7}, {%8,%9}, {%0,%1,%2,%3};"
        : "+f"(d[0]), "+f"(d[1]), "+f"(d[2]), "+f"(d[3])
        : "r"(a[0]), "r"(a[1]), "r"(a[2]), "r"(a[3]), "r"(b0), "r"(b1));
}

// ---------------- mask expansion: rowscale[r = pos*B + b] = mask[b][pos] ? 0 : 1
__global__ void expand_mask_kernel(const int* __restrict__ mask,
                                   float* __restrict__ rowscale, int L) {
    int r = blockIdx.x * blockDim.x + threadIdx.x;
    if (r < L * BB) {
        int pos = r / BB, b = r % BB;
        rowscale[r] = mask[b * L + pos] ? 0.f : 1.f;
    }
}

// =====================================================================
// TF32 GEMM: C[M,N] = A[M,K] @ W[N,K]^T + bias   (opt relu, opt rowscale on A)
// 128x128x32 block tile, 256 threads, 8 warps (4m x 2n), warp tile 32x64.
// =====================================================================
#define SKEW 36
__global__ __launch_bounds__(256) void gemm_tf32_kernel(
    const float* __restrict__ A, const float* __restrict__ W,
    const float* __restrict__ bias, const float* __restrict__ rowscale,
    float* __restrict__ C, int M, int N, int K, int relu)
{
    __shared__ uint32_t As[128][SKEW];
    __shared__ uint32_t Ws[128][SKEW];
    const int tid = threadIdx.x;
    const int lane = tid & 31, warp = tid >> 5;
    const int wm = warp & 3, wn = warp >> 2;
    const int g = lane >> 2, tig = lane & 3;
    const int bx = blockIdx.x, by = blockIdx.y;

    float d[2][8][4];
    #pragma unroll
    for (int mt = 0; mt < 2; mt++)
        #pragma unroll
        for (int nt = 0; nt < 8; nt++)
            #pragma unroll
            for (int i = 0; i < 4; i++) d[mt][nt][i] = 0.f;

    // prefetch registers
    float4 aReg[4], wReg[4];
    const int r_ld  = tid >> 3;            // 0..31 per 256? no: f>>3 below
    (void)r_ld;

    float ascale[4];
    int arow[4], wrow[4], acol[4], wcol[4];
    #pragma unroll
    for (int i = 0; i < 4; i++) {
        int f = tid + (i << 8);
        int r = f >> 3;
        int c4 = (f & 7) << 2;
        arow[i] = by * 128 + r; acol[i] = c4;
        wrow[i] = bx * 128 + r; wcol[i] = c4;
        ascale[i] = rowscale ? rowscale[arow[i]] : 1.f;
    }

    auto load_regs = [&](int k0) {
        #pragma unroll
        for (int i = 0; i < 4; i++) {
            aReg[i] = *(const float4*)(A + (size_t)arow[i] * K + k0 + acol[i]);
            wReg[i] = *(const float4*)(W + (size_t)wrow[i] * K + k0 + wcol[i]);
        }
    };
    auto store_smem = [&]() {
        #pragma unroll
        for (int i = 0; i < 4; i++) {
            int f = tid + (i << 8);
            int r = f >> 3;
            int c4 = (f & 7) << 2;
            float s = ascale[i];
            As[r][c4 + 0] = f2tf32(aReg[i].x * s);
            As[r][c4 + 1] = f2tf32(aReg[i].y * s);
            As[r][c4 + 2] = f2tf32(aReg[i].z * s);
            As[r][c4 + 3] = f2tf32(aReg[i].w * s);
            Ws[r][c4 + 0] = f2tf32(wReg[i].x);
            Ws[r][c4 + 1] = f2tf32(wReg[i].y);
            Ws[r][c4 + 2] = f2tf32(wReg[i].z);
            Ws[r][c4 + 3] = f2tf32(wReg[i].w);
        }
    };

    load_regs(0);
    store_smem();
    __syncthreads();

    for (int k0 = 0; k0 < K; k0 += 32) {
        bool has_next = (k0 + 32) < K;
        if (has_next) load_regs(k0 + 32);

        #pragma unroll
        for (int ks = 0; ks < 4; ks++) {
            int kb = ks * 8;
            uint32_t af[2][4];
            #pragma unroll
            for (int mt = 0; mt < 2; mt++) {
                int ar = wm * 32 + mt * 16 + g;
                af[mt][0] = As[ar][kb + tig];
                af[mt][1] = As[ar + 8][kb + tig];
                af[mt][2] = As[ar][kb + tig + 4];
                af[mt][3] = As[ar + 8][kb + tig + 4];
            }
            #pragma unroll
            for (int nt = 0; nt < 8; nt++) {
                int bc = wn * 64 + nt * 8 + g;
                uint32_t b0 = Ws[bc][kb + tig];
                uint32_t b1 = Ws[bc][kb + tig + 4];
                mma_tf32(d[0][nt], af[0], b0, b1);
                mma_tf32(d[1][nt], af[1], b0, b1);
            }
        }

        if (has_next) {
            __syncthreads();
            store_smem();
            __syncthreads();
        }
    }

    // epilogue
    #pragma unroll
    for (int mt = 0; mt < 2; mt++) {
        int row0 = by * 128 + wm * 32 + mt * 16 + g;
        #pragma unroll
        for (int nt = 0; nt < 8; nt++) {
            int col = bx * 128 + wn * 64 + nt * 8 + tig * 2;
            float b0 = bias[col], b1 = bias[col + 1];
            float v00 = d[mt][nt][0] + b0, v01 = d[mt][nt][1] + b1;
            float v10 = d[mt][nt][2] + b0, v11 = d[mt][nt][3] + b1;
            if (relu) {
                v00 = fmaxf(v00, 0.f); v01 = fmaxf(v01, 0.f);
                v10 = fmaxf(v10, 0.f); v11 = fmaxf(v11, 0.f);
            }
            *(float2*)(C + (size_t)row0 * N + col)       = make_float2(v00, v01);
            *(float2*)(C + (size_t)(row0 + 8) * N + col) = make_float2(v10, v11);
        }
    }
}

// =====================================================================
// TF32 attention scores: Sc[bh,t,s] = scale * (Q_bh @ K_bh^T) + mask[t,s]
// per (b,h): Q rows strided by B*D.  128x128 tile, K=64.
// =====================================================================
__global__ __launch_bounds__(256) void scores_tf32_kernel(
    const float* __restrict__ Q, const float* __restrict__ Kk,
    const float* __restrict__ mask, float* __restrict__ Sc, float scale)
{
    __shared__ uint32_t As[128][SKEW];
    __shared__ uint32_t Ws[128][SKEW];
    const int tid = threadIdx.x;
    const int lane = tid & 31, warp = tid >> 5;
    const int wm = warp & 3, wn = warp >> 2;
    const int g = lane >> 2, tig = lane & 3;
    const int bh = blockIdx.z;
    const int b = bh / HH, h = bh % HH;
    const int t0 = blockIdx.y * 128, s0 = blockIdx.x * 128;

    float d[2][8][4];
    #pragma unroll
    for (int mt = 0; mt < 2; mt++)
        #pragma unroll
        for (int nt = 0; nt < 8; nt++)
            #pragma unroll
            for (int i = 0; i < 4; i++) d[mt][nt][i] = 0.f;

    for (int k0 = 0; k0 < HDD; k0 += 32) {
        #pragma unroll
        for (int i = 0; i < 4; i++) {
            int f = tid + (i << 8);
            int r = f >> 3;
            int c4 = (f & 7) << 2;
            float4 q4 = *(const float4*)(Q + ((size_t)(t0 + r) * BB + b) * DD + h * HDD + k0 + c4);
            As[r][c4 + 0] = f2tf32(q4.x); As[r][c4 + 1] = f2tf32(q4.y);
            As[r][c4 + 2] = f2tf32(q4.z); As[r][c4 + 3] = f2tf32(q4.w);
            float4 k4 = *(const float4*)(Kk + ((size_t)(s0 + r) * BB + b) * DD + h * HDD + k0 + c4);
            Ws[r][c4 + 0] = f2tf32(k4.x); Ws[r][c4 + 1] = f2tf32(k4.y);
            Ws[r][c4 + 2] = f2tf32(k4.z); Ws[r][c4 + 3] = f2tf32(k4.w);
        }
        __syncthreads();

        #pragma unroll
        for (int ks = 0; ks < 4; ks++) {
            int kb = ks * 8;
            uint32_t af[2][4];
            #pragma unroll
            for (int mt = 0; mt < 2; mt++) {
                int ar = wm * 32 + mt * 16 + g;
                af[mt][0] = As[ar][kb + tig];
                af[mt][1] = As[ar + 8][kb + tig];
                af[mt][2] = As[ar][kb + tig + 4];
                af[mt][3] = As[ar + 8][kb + tig + 4];
            }
            #pragma unroll
            for (int nt = 0; nt < 8; nt++) {
                int bc = wn * 64 + nt * 8 + g;
                uint32_t b0 = Ws[bc][kb + tig];
                uint32_t b1 = Ws[bc][kb + tig + 4];
                mma_tf32(d[0][nt], af[0], b0, b1);
                mma_tf32(d[1][nt], af[1], b0, b1);
            }
        }
        __syncthreads();
    }

    #pragma unroll
    for (int mt = 0; mt < 2; mt++) {
        int t = t0 + wm * 32 + mt * 16 + g;
        #pragma unroll
        for (int nt = 0; nt < 8; nt++) {
            int s = s0 + wn * 64 + nt * 8 + tig * 2;
            float m00 = 0.f, m01 = 0.f, m10 = 0.f, m11 = 0.f;
            if (mask) {
                m00 = mask[(size_t)t * TT + s];       m01 = mask[(size_t)t * TT + s + 1];
                m10 = mask[(size_t)(t + 8) * TT + s]; m11 = mask[(size_t)(t + 8) * TT + s + 1];
            }
            float* p0 = Sc + ((size_t)bh * TT + t) * SSZ + s;
            float* p1 = Sc + ((size_t)bh * TT + t + 8) * SSZ + s;
            *(float2*)p0 = make_float2(d[mt][nt][0] * scale + m00, d[mt][nt][1] * scale + m01);
            *(float2*)p1 = make_float2(d[mt][nt][2] * scale + m10, d[mt][nt][3] * scale + m11);
        }
    }
}

// =====================================================================
// TF32 ctx: ctx[t, hd] = P[t,:] @ V'[:,hd] per (b,h); V'[s][hd] strided.
// 128(m) x 64(n) x 32(k) tile; warp tile 32x32. Writes ctx and optional attn.
// =====================================================================
__global__ __launch_bounds__(256) void ctx_tf32_kernel(
    const float* __restrict__ P, const float* __restrict__ V,
    float* __restrict__ ctx, float* __restrict__ attn)
{
    __shared__ uint32_t As[128][SKEW];
    __shared__ uint32_t Ws[64][SKEW];
    const int tid = threadIdx.x;
    const int lane = tid & 31, warp = tid >> 5;
    const int wm = warp & 3, wn = warp >> 2;
    const int g = lane >> 2, tig = lane & 3;
    const int bh = blockIdx.y;
    const int b = bh / HH, h = bh % HH;
    const int t0 = blockIdx.x * 128;
    const float* Pb = P + (size_t)bh * TT * SSZ;

    float d[2][4][4];
    #pragma unroll
    for (int mt = 0; mt < 2; mt++)
        #pragma unroll
        for (int nt = 0; nt < 4; nt++)
            #pragma unroll
            for (int i = 0; i < 4; i++) d[mt][nt][i] = 0.f;

    for (int k0 = 0; k0 < SSZ; k0 += 32) {
        // A tile: P rows t0..t0+127, cols k0..k0+31
        #pragma unroll
        for (int i = 0; i < 4; i++) {
            int f = tid + (i << 8);
            int r = f >> 3;
            int c4 = (f & 7) << 2;
            float4 p4 = *(const float4*)(Pb + (size_t)(t0 + r) * SSZ + k0 + c4);
            As[r][c4 + 0] = f2tf32(p4.x); As[r][c4 + 1] = f2tf32(p4.y);
            As[r][c4 + 2] = f2tf32(p4.z); As[r][c4 + 3] = f2tf32(p4.w);
        }
        // W tile (transposed store): Ws[n][k] = V[(k0+k)*B+b][h*64+n]
        #pragma unroll
        for (int i = 0; i < 2; i++) {
            int f = tid + (i << 8);
            int kr = f >> 4;
            int n4 = (f & 15) << 2;
            float4 v4 = *(const float4*)(V + ((size_t)(k0 + kr) * BB + b) * DD + h * HDD + n4);
            Ws[n4 + 0][kr] = f2tf32(v4.x);
            Ws[n4 + 1][kr] = f2tf32(v4.y);
            Ws[n4 + 2][kr] = f2tf32(v4.z);
            Ws[n4 + 3][kr] = f2tf32(v4.w);
        }
        __syncthreads();

        #pragma unroll
        for (int ks = 0; ks < 4; ks++) {
            int kb = ks * 8;
            uint32_t af[2][4];
            #pragma unroll
            for (int mt = 0; mt < 2; mt++) {
                int ar = wm * 32 + mt * 16 + g;
                af[mt][0] = As[ar][kb + tig];
                af[mt][1] = As[ar + 8][kb + tig];
                af[mt][2] = As[ar][kb + tig + 4];
                af[mt][3] = As[ar + 8][kb + tig + 4];
            }
            #pragma unroll
            for (int nt = 0; nt < 4; nt++) {
                int bc = wn * 32 + nt * 8 + g;
                uint32_t b0 = Ws[bc][kb + tig];
                uint32_t b1 = Ws[bc][kb + tig + 4];
                mma_tf32(d[0][nt], af[0], b0, b1);
                mma_tf32(d[1][nt], af[1], b0, b1);
            }
        }
        __syncthreads();
    }

    #pragma unroll
    for (int mt = 0; mt < 2; mt++) {
        int t = t0 + wm * 32 + mt * 16 + g;
        #pragma unroll
        for (int nt = 0; nt < 4; nt++) {
            int hd = wn * 32 + nt * 8 + tig * 2;
            float2 v0 = make_float2(d[mt][nt][0], d[mt][nt][1]);
            float2 v1 = make_float2(d[mt][nt][2], d[mt][nt][3]);
            *(float2*)(ctx + ((size_t)t * BB + b) * DD + h * HDD + hd)       = v0;
            *(float2*)(ctx + ((size_t)(t + 8) * BB + b) * DD + h * HDD + hd) = v1;
            if (attn) {
                *(float2*)(attn + (((size_t)h * BB + b) * TT + t) * HDD + hd)       = v0;
                *(float2*)(attn + (((size_t)h * BB + b) * TT + t + 8) * HDD + hd) = v1;
            }
        }
    }
}

// ---------------- softmax over last dim (1024), one block per row
__global__ __launch_bounds__(256) void softmax_kernel(float* __restrict__ Sc) {
    float* p = Sc + (size_t)blockIdx.x * SSZ;
    int tid = threadIdx.x;
    float4 v = *(float4*)(p + tid * 4);
    float m = fmaxf(fmaxf(v.x, v.y), fmaxf(v.z, v.w));
    m = block_max(m);
    float e0 = __expf(v.x - m), e1 = __expf(v.y - m);
    float e2 = __expf(v.z - m), e3 = __expf(v.w - m);
    float s = block_sum(e0 + e1 + e2 + e3);
    float inv = 1.f / s;
    float4 o; o.x = e0 * inv; o.y = e1 * inv; o.z = e2 * inv; o.w = e3 * inv;
    *(float4*)(p + tid * 4) = o;
}

// ---------------- fused residual add + layernorm (one block per row of 1024)
__global__ __launch_bounds__(256) void add_ln_kernel(
    const float* __restrict__ a, const float* __restrict__ r,
    const float* __restrict__ g, const float* __restrict__ be,
    float* __restrict__ o)
{
    size_t row = blockIdx.x;
    int tid = threadIdx.x;
    float4 va = *(const float4*)(a + row * DD + tid * 4);
    float4 vr = *(const float4*)(r + row * DD + tid * 4);
    float x0 = va.x + vr.x, x1 = va.y + vr.y, x2 = va.z + vr.z, x3 = va.w + vr.w;
    float s  = block_sum(x0 + x1 + x2 + x3);
    float mu = s * (1.f / DD);
    float d0 = x0 - mu, d1 = x1 - mu, d2 = x2 - mu, d3 = x3 - mu;
    float sq = block_sum(d0 * d0 + d1 * d1 + d2 * d2 + d3 * d3);
    float inv = rsqrtf(sq * (1.f / DD) + 1e-5f);
    float4 vg = *(const float4*)(g + tid * 4);
    float4 vb = *(const float4*)(be + tid * 4);
    float4 out;
    out.x = d0 * inv * vg.x + vb.x;
    out.y = d1 * inv * vg.y + vb.y;
    out.z = d2 * inv * vg.z + vb.z;
    out.w = d3 * inv * vg.w + vb.w;
    *(float4*)(o + row * DD + tid * 4) = out;
}

// ---------------- host launch ----------------
extern "C" void kernel_launch(void* const* d_in, const int* in_sizes, int n_in,
                              void* d_out, int out_size)
{
    const float* state = (const float*)d_in[0];
    const float* enc   = (const float*)d_in[1];
    const float* amask = (const float*)d_in[2];
    const int* spad = (const int*)d_in[3];
    const int* epad = (const int*)d_in[4];
    const float *saWq = (const float*)d_in[5],  *sabq = (const float*)d_in[6];
    const float *saWk = (const float*)d_in[7],  *sabk = (const float*)d_in[8];
    const float *saWv = (const float*)d_in[9],  *sabv = (const float*)d_in[10];
    const float *saWo = (const float*)d_in[11], *sabo = (const float*)d_in[12];
    const float *eaWq = (const float*)d_in[13], *eabq = (const float*)d_in[14];
    const float *eaWk = (const float*)d_in[15], *eabk = (const float*)d_in[16];
    const float *eaWv = (const float*)d_in[17], *eabv = (const float*)d_in[18];
    const float *eaWo = (const float*)d_in[19], *eabo = (const float*)d_in[20];
    const float *ln1g = (const float*)d_in[21], *ln1b = (const float*)d_in[22];
    const float *ln2g = (const float*)d_in[23], *ln2b = (const float*)d_in[24];
    const float *ln3g = (const float*)d_in[25], *ln3b = (const float*)d_in[26];
    const float *fc1W = (const float*)d_in[27], *fc1b = (const float*)d_in[28];
    const float *fc2W = (const float*)d_in[29], *fc2b = (const float*)d_in[30];

    float *q, *k, *v, *ctx, *tmp, *x1, *x2, *ffn, *sc, *rss, *rse;
    cudaGetSymbolAddress((void**)&q,   g_q);
    cudaGetSymbolAddress((void**)&k,   g_k);
    cudaGetSymbolAddress((void**)&v,   g_v);
    cudaGetSymbolAddress((void**)&ctx, g_ctx);
    cudaGetSymbolAddress((void**)&tmp, g_tmp);
    cudaGetSymbolAddress((void**)&x1,  g_x1);
    cudaGetSymbolAddress((void**)&x2,  g_x2);
    cudaGetSymbolAddress((void**)&ffn, g_ffn);
    cudaGetSymbolAddress((void**)&sc,  g_scores);
    cudaGetSymbolAddress((void**)&rss, g_rs_self);
    cudaGetSymbolAddress((void**)&rse, g_rs_enc);

    float* outx = (float*)d_out;
    float* outa = outx + (size_t)MM * DD;

    const float scale = 0.125f;  // 1/sqrt(64)

    expand_mask_kernel<<<(MM + 255) / 256, 256>>>(spad, rss, TT);
    expand_mask_kernel<<<(MM + 255) / 256, 256>>>(epad, rse, SSZ);

    dim3 gProj(DD / 128, MM / 128);            // (8, 32)
    dim3 gF1(FFND / 128, MM / 128);            // (32, 32)
    dim3 gSc(SSZ / 128, TT / 128, BB * HH);    // (8, 8, 64)
    dim3 gCtx(TT / 128, BB * HH);              // (8, 64)

    // ---- self-attention block ----
    gemm_tf32_kernel<<<gProj, 256>>>(state, saWq, sabq, nullptr, q, MM, DD, DD, 0);
    gemm_tf32_kernel<<<gProj, 256>>>(state, saWk, sabk, rss,     k, MM, DD, DD, 0);
    gemm_tf32_kernel<<<gProj, 256>>>(state, saWv, sabv, nullptr, v, MM, DD, DD, 0);
    scores_tf32_kernel<<<gSc, 256>>>(q, k, amask, sc, scale);
    softmax_kernel<<<BB * HH * TT, 256>>>(sc);
    ctx_tf32_kernel<<<gCtx, 256>>>(sc, v, ctx, nullptr);
    gemm_tf32_kernel<<<gProj, 256>>>(ctx, saWo, sabo, nullptr, tmp, MM, DD, DD, 0);
    add_ln_kernel<<<MM, 256>>>(tmp, state, ln1g, ln1b, x1);

    // ---- encoder-decoder attention block ----
    gemm_tf32_kernel<<<gProj, 256>>>(x1,  eaWq, eabq, nullptr, q, MM, DD, DD, 0);
    gemm_tf32_kernel<<<gProj, 256>>>(enc, eaWk, eabk, rse,     k, MM, DD, DD, 0);
    gemm_tf32_kernel<<<gProj, 256>>>(enc, eaWv, eabv, nullptr, v, MM, DD, DD, 0);
    scores_tf32_kernel<<<gSc, 256>>>(q, k, nullptr, sc, scale);
    softmax_kernel<<<BB * HH * TT, 256>>>(sc);
    ctx_tf32_kernel<<<gCtx, 256>>>(sc, v, ctx, outa);
    gemm_tf32_kernel<<<gProj, 256>>>(ctx, eaWo, eabo, nullptr, tmp, MM, DD, DD, 0);
    add_ln_kernel<<<MM, 256>>>(tmp, x1, ln2g, ln2b, x2);

    // ---- FFN block ----
    gemm_tf32_kernel<<<gF1, 256>>>(x2, fc1W, fc1b, nullptr, ffn, MM, FFND, DD, 1);
    gemm_tf32_kernel<<<gProj, 256>>>(ffn, fc2W, fc2b, nullptr, tmp, MM, DD, FFND, 0);
    add_ln_kernel<<<MM, 256>>>(tmp, x2, ln3g, ln3b, outx);
}